// round 5
// baseline (speedup 1.0000x reference)
#include <cuda_runtime.h>
#include <cuda_fp16.h>
#include <cstdint>

#define NV  400000
#define ND  16
#define TPB 128
#define VPB 256   // vertices per block = 2 per thread

// Packed per-vertex coords: {src.x,src.y,src.z,trg.x,trg.y,trg.z} as 6 fp16 + pad = 16B.
__device__ uint4 g_packed[NV];
__device__ float g_num, g_den;
__device__ unsigned int g_count;

__device__ __forceinline__ unsigned int h2bits(__half2 h) {
    return *reinterpret_cast<unsigned int*>(&h);
}

__device__ __forceinline__ void unpack6(uint4 p, float& a, float& b, float& c,
                                        float& d, float& e, float& f) {
    float2 f0 = __half22float2(*reinterpret_cast<__half2*>(&p.x));
    float2 f1 = __half22float2(*reinterpret_cast<__half2*>(&p.y));
    float2 f2 = __half22float2(*reinterpret_cast<__half2*>(&p.z));
    a = f0.x; b = f0.y; c = f1.x; d = f1.y; e = f2.x; f = f2.y;
}

__device__ __forceinline__ uint4 make_packed(float sx, float sy, float sz,
                                             float tx, float ty, float tz) {
    uint4 p;
    p.x = h2bits(__floats2half2_rn(sx, sy));
    p.y = h2bits(__floats2half2_rn(sz, tx));
    p.z = h2bits(__floats2half2_rn(ty, tz));
    p.w = 0u;
    return p;
}

__global__ void pack_kernel(const float* __restrict__ trg,
                            const float* __restrict__ src, int V) {
    int t = blockIdx.x * blockDim.x + threadIdx.x;
    if (t == 0) { g_num = 0.f; g_den = 0.f; g_count = 0u; }
    int v0 = t * 4;
    if (v0 >= V) return;
    if (v0 + 4 <= V) {
        const float4* s4 = reinterpret_cast<const float4*>(src + (size_t)v0 * 3);
        const float4* t4 = reinterpret_cast<const float4*>(trg + (size_t)v0 * 3);
        float4 a = s4[0], b = s4[1], c = s4[2];
        float4 d = t4[0], e = t4[1], f = t4[2];
        g_packed[v0+0] = make_packed(a.x, a.y, a.z, d.x, d.y, d.z);
        g_packed[v0+1] = make_packed(a.w, b.x, b.y, d.w, e.x, e.y);
        g_packed[v0+2] = make_packed(b.z, b.w, c.x, e.z, e.w, f.x);
        g_packed[v0+3] = make_packed(c.y, c.z, c.w, f.y, f.z, f.w);
    } else {
        for (int v = v0; v < V; v++) {
            g_packed[v] = make_packed(src[3*v], src[3*v+1], src[3*v+2],
                                      trg[3*v], trg[3*v+1], trg[3*v+2]);
        }
    }
}

// Two vertices per thread (ILP-2): gathers from both vertices interleaved
// (MLP=8 sustained), polar Newton chains interleaved (fills FFMA latency),
// residual pass interleaved. All loads use clamped vertex ids; invalid
// lanes are masked out of the final accumulation (branchless, no OOB).
__global__ void __launch_bounds__(TPB, 4)
rigid_kernel(const int* __restrict__ nbr,
             const float* __restrict__ wts,
             float* __restrict__ out, int V) {
    __shared__ uint2 sh64[2 * ND * TPB];          // 32 KB: {s0s1, s2t0}
    __shared__ unsigned int sh32[2 * ND * TPB];   // 16 KB: {t1t2}
    __shared__ float red[8];
    const int tid = threadIdx.x;
    const int vb = blockIdx.x * VPB;

    int   vv[2];  vv[0] = vb + tid;  vv[1] = vb + TPB + tid;
    float msk[2];
    int   uu[2];
    #pragma unroll
    for (int u = 0; u < 2; u++) {
        msk[u] = (vv[u] < V) ? 1.f : 0.f;
        uu[u]  = (vv[u] < V) ? vv[u] : 0;
    }

    float csx[2], csy[2], csz[2], ctx[2], cty[2], ctz[2];
    #pragma unroll
    for (int u = 0; u < 2; u++)
        unpack6(g_packed[uu[u]], csx[u], csy[u], csz[u], ctx[u], cty[u], ctz[u]);

    const int4* ip0 = reinterpret_cast<const int4*>(nbr + (long long)uu[0] * ND);
    const int4* ip1 = reinterpret_cast<const int4*>(nbr + (long long)uu[1] * ND);

    float m[2][9];
    #pragma unroll
    for (int u = 0; u < 2; u++)
        #pragma unroll
        for (int i = 0; i < 9; i++) m[u][i] = 0.f;

    // Pass 1: 4 chunks; each chunk gathers 4 neighbors of each vertex (8 LDG.128
    // in flight), accumulates both covariances, caches (s,t) fp16 in smem.
    #pragma unroll
    for (int k = 0; k < 4; k++) {
        int4 qa = ip0[k];
        int4 qb = ip1[k];
        int ia[4], ib[4];
        ia[0]=min(max(qa.x,0),V-1); ia[1]=min(max(qa.y,0),V-1);
        ia[2]=min(max(qa.z,0),V-1); ia[3]=min(max(qa.w,0),V-1);
        ib[0]=min(max(qb.x,0),V-1); ib[1]=min(max(qb.y,0),V-1);
        ib[2]=min(max(qb.z,0),V-1); ib[3]=min(max(qb.w,0),V-1);
        uint4 pa[4], pb[4];
        #pragma unroll
        for (int j = 0; j < 4; j++) { pa[j] = g_packed[ia[j]]; pb[j] = g_packed[ib[j]]; }
        #pragma unroll
        for (int j = 0; j < 4; j++) {
            int d = k * 4 + j;
            // vertex A
            {
                float a,b,c,e,f,g;
                unpack6(pa[j], a, b, c, e, f, g);
                float s0=a-csx[0], s1=b-csy[0], s2=c-csz[0];
                float t0=e-ctx[0], t1=f-cty[0], t2=g-ctz[0];
                m[0][0]=fmaf(s0,t0,m[0][0]); m[0][1]=fmaf(s0,t1,m[0][1]); m[0][2]=fmaf(s0,t2,m[0][2]);
                m[0][3]=fmaf(s1,t0,m[0][3]); m[0][4]=fmaf(s1,t1,m[0][4]); m[0][5]=fmaf(s1,t2,m[0][5]);
                m[0][6]=fmaf(s2,t0,m[0][6]); m[0][7]=fmaf(s2,t1,m[0][7]); m[0][8]=fmaf(s2,t2,m[0][8]);
                uint2 w;
                w.x = h2bits(__floats2half2_rn(s0, s1));
                w.y = h2bits(__floats2half2_rn(s2, t0));
                sh64[d*TPB + tid] = w;
                sh32[d*TPB + tid] = h2bits(__floats2half2_rn(t1, t2));
            }
            // vertex B
            {
                float a,b,c,e,f,g;
                unpack6(pb[j], a, b, c, e, f, g);
                float s0=a-csx[1], s1=b-csy[1], s2=c-csz[1];
                float t0=e-ctx[1], t1=f-cty[1], t2=g-ctz[1];
                m[1][0]=fmaf(s0,t0,m[1][0]); m[1][1]=fmaf(s0,t1,m[1][1]); m[1][2]=fmaf(s0,t2,m[1][2]);
                m[1][3]=fmaf(s1,t0,m[1][3]); m[1][4]=fmaf(s1,t1,m[1][4]); m[1][5]=fmaf(s1,t2,m[1][5]);
                m[1][6]=fmaf(s2,t0,m[1][6]); m[1][7]=fmaf(s2,t1,m[1][7]); m[1][8]=fmaf(s2,t2,m[1][8]);
                uint2 w;
                w.x = h2bits(__floats2half2_rn(s0, s1));
                w.y = h2bits(__floats2half2_rn(s2, t0));
                sh64[(ND + d)*TPB + tid] = w;
                sh32[(ND + d)*TPB + tid] = h2bits(__floats2half2_rn(t1, t2));
            }
        }
    }
    #pragma unroll
    for (int u = 0; u < 2; u++) { m[u][0] += 1e-6f; m[u][4] += 1e-6f; m[u][8] += 1e-6f; }

    // Polar factor via det-scaled Newton, two independent chains interleaved.
    float x[2][9];
    #pragma unroll
    for (int u = 0; u < 2; u++)
        #pragma unroll
        for (int i = 0; i < 9; i++) x[u][i] = m[u][i];

    #pragma unroll
    for (int it = 0; it < 6; it++) {
        float c[2][9], aa[2], bb[2];
        #pragma unroll
        for (int u = 0; u < 2; u++) {
            c[u][0]=fmaf(x[u][4],x[u][8],-x[u][5]*x[u][7]);
            c[u][1]=fmaf(x[u][5],x[u][6],-x[u][3]*x[u][8]);
            c[u][2]=fmaf(x[u][3],x[u][7],-x[u][4]*x[u][6]);
            c[u][3]=fmaf(x[u][2],x[u][7],-x[u][1]*x[u][8]);
            c[u][4]=fmaf(x[u][0],x[u][8],-x[u][2]*x[u][6]);
            c[u][5]=fmaf(x[u][1],x[u][6],-x[u][0]*x[u][7]);
            c[u][6]=fmaf(x[u][1],x[u][5],-x[u][2]*x[u][4]);
            c[u][7]=fmaf(x[u][2],x[u][3],-x[u][0]*x[u][5]);
            c[u][8]=fmaf(x[u][0],x[u][4],-x[u][1]*x[u][3]);
            float det = fmaf(x[u][0],c[u][0], fmaf(x[u][1],c[u][1], x[u][2]*c[u][2]));
            float ad  = fmaxf(fabsf(det), 1e-30f);
            float mu  = __powf(ad, -0.33333334f);
            aa[u] = 0.5f * mu;
            bb[u] = 0.5f / (mu * det);
        }
        #pragma unroll
        for (int u = 0; u < 2; u++)
            #pragma unroll
            for (int i = 0; i < 9; i++)
                x[u][i] = fmaf(aa[u], x[u][i], bb[u]*c[u][i]);
    }

    // Pass 2: residuals from smem cache, both vertices interleaved.
    const float4* wp0 = reinterpret_cast<const float4*>(wts + (long long)uu[0] * ND);
    const float4* wp1 = reinterpret_cast<const float4*>(wts + (long long)uu[1] * ND);
    float num[2] = {0.f, 0.f}, den[2] = {0.f, 0.f};
    #pragma unroll
    for (int k = 0; k < 4; k++) {
        float4 w4a = wp0[k];
        float4 w4b = wp1[k];
        den[0] += (w4a.x + w4a.y) + (w4a.z + w4a.w);
        den[1] += (w4b.x + w4b.y) + (w4b.z + w4b.w);
        float wa[4] = {w4a.x, w4a.y, w4a.z, w4a.w};
        float wb[4] = {w4b.x, w4b.y, w4b.z, w4b.w};
        #pragma unroll
        for (int j = 0; j < 4; j++) {
            int d = k * 4 + j;
            #pragma unroll
            for (int u = 0; u < 2; u++) {
                uint2 p  = sh64[(u*ND + d)*TPB + tid];
                unsigned int p2 = sh32[(u*ND + d)*TPB + tid];
                float2 f0 = __half22float2(*reinterpret_cast<__half2*>(&p.x));
                float2 f1 = __half22float2(*reinterpret_cast<__half2*>(&p.y));
                float2 f2 = __half22float2(*reinterpret_cast<__half2*>(&p2));
                float s0=f0.x, s1=f0.y, s2=f1.x, t0=f1.y, t1=f2.x, t2=f2.y;
                float y0 = fmaf(x[u][0],s0, fmaf(x[u][1],s1, x[u][2]*s2)) - t0;
                float y1 = fmaf(x[u][3],s0, fmaf(x[u][4],s1, x[u][5]*s2)) - t1;
                float y2 = fmaf(x[u][6],s0, fmaf(x[u][7],s1, x[u][8]*s2)) - t2;
                float dd = __fsqrt_rn(fmaf(y0,y0, fmaf(y1,y1, y2*y2)));
                float w  = (u == 0) ? wa[j] : wb[j];
                num[u] = fmaf(dd, w, num[u]);
            }
        }
    }

    float tnum = msk[0]*num[0] + msk[1]*num[1];
    float tden = msk[0]*den[0] + msk[1]*den[1];

    // Block reduction (4 warps).
    #pragma unroll
    for (int o = 16; o > 0; o >>= 1) {
        tnum += __shfl_down_sync(0xffffffffu, tnum, o);
        tden += __shfl_down_sync(0xffffffffu, tden, o);
    }
    int warp = tid >> 5;
    if ((tid & 31) == 0) { red[warp] = tnum; red[4 + warp] = tden; }
    __syncthreads();
    if (tid == 0) {
        float n = 0.f, dn = 0.f;
        #pragma unroll
        for (int i = 0; i < 4; i++) { n += red[i]; dn += red[4 + i]; }
        atomicAdd(&g_num, n);
        atomicAdd(&g_den, dn);
        __threadfence();
        unsigned int done = atomicAdd(&g_count, 1u);
        if (done == gridDim.x - 1) {   // last block finalizes
            float fn = atomicAdd(&g_num, 0.f);
            float fd = atomicAdd(&g_den, 0.f);
            out[0] = fn / (fd + 1e-6f);
        }
    }
}

extern "C" void kernel_launch(void* const* d_in, const int* in_sizes, int n_in,
                              void* d_out, int out_size) {
    const float* trg = (const float*)d_in[0];      // new_verts_coords
    const float* src = (const float*)d_in[1];      // verts_src
    const int*   nbr = (const int*)d_in[2];        // neighborhood_indices (int32)
    const float* wts = (const float*)d_in[3];      // neighborhood_weights
    float* out = (float*)d_out;

    int V = in_sizes[0] / 3;
    int grid = (V + VPB - 1) / VPB;
    int pack_grid = ((V + 3) / 4 + TPB - 1) / TPB;

    pack_kernel<<<pack_grid, TPB>>>(trg, src, V);
    rigid_kernel<<<grid, TPB>>>(nbr, wts, out, V);
}